// round 1
// baseline (speedup 1.0000x reference)
#include <cuda_runtime.h>

// GConvLSTM (ChebConv K=1) fused cell + linear head.
// edge_index / edge_weight unused (K=1 degenerates to dense x@W + b).
//
// N = 1e6 nodes, F_IN = 8, H = 32, OUT = 9.
// Outputs (concatenated): y[N,9], h0[N,32], c0[N,32].

#define FIN   8
#define HDIM  32
#define OUTD  9
#define KTOT  (FIN + HDIM)   // 40 floats per (gate, channel) weight row
#define KPAIR (KTOT / 2)     // 20 f32x2 pairs
#define TPB   256

// ---------------- fast math helpers (MUFU) ----------------
__device__ __forceinline__ float fast_ex2(float x) {
    float r; asm("ex2.approx.f32 %0, %1;" : "=f"(r) : "f"(x)); return r;
}
__device__ __forceinline__ float fast_rcp(float x) {
    float r; asm("rcp.approx.f32 %0, %1;" : "=f"(r) : "f"(x)); return r;
}
// sigmoid(v) = 1 / (1 + 2^(-v*log2(e)))
__device__ __forceinline__ float sigmoid_f(float v) {
    return fast_rcp(1.0f + fast_ex2(-1.4426950408889634f * v));
}
// tanh(v) = 1 - 2 / (1 + 2^(2v*log2(e)))
__device__ __forceinline__ float tanh_f(float v) {
    return 1.0f - 2.0f * fast_rcp(1.0f + fast_ex2(2.8853900817779268f * v));
}

// ---------------- packed f32x2 FMA ----------------
__device__ __forceinline__ void ffma2(unsigned long long& acc,
                                      unsigned long long a,
                                      unsigned long long b) {
    asm("fma.rn.f32x2 %0, %1, %2, %0;" : "+l"(acc) : "l"(a), "l"(b));
}
__device__ __forceinline__ void unpack2(unsigned long long v, float& lo, float& hi) {
    unsigned int a, b;
    asm("mov.b64 {%0, %1}, %2;" : "=r"(a), "=r"(b) : "l"(v));
    lo = __uint_as_float(a);
    hi = __uint_as_float(b);
}

struct Params {
    const float* x;
    const float* h;
    const float* c;
    const float* Wx[4];   // i, f, c, o   shape [FIN, H] row-major
    const float* bx[4];
    const float* Wh[4];   // [H, H]
    const float* bh[4];
    const float* b[4];
    const float* wc[4];   // peephole; wc[2] == nullptr (cell gate has none)
    const float* Wl;      // [H, OUT]
    const float* bl;      // [OUT]
    float* y;             // [N, OUT]
    float* h0;            // [N, H]
    float* c0;            // [N, H]
    int N;
};

__global__ void __launch_bounds__(TPB, 2)
gconv_lstm_kernel(Params P) {
    // ---- shared weight staging (transposed so channel j is a contiguous row) ----
    __shared__ float sW[4][HDIM][KTOT];  // [gate][j][k]: k<8 = Wx col j, k>=8 = Wh col j
    __shared__ float sB[4][HDIM];        // bx + bh + b  combined
    __shared__ float sC[4][HDIM];        // peephole (gate 2 = zeros)
    __shared__ float sL[HDIM][12];       // Wl rows padded 9 -> 12
    __shared__ float sBl[12];

    const int tid = threadIdx.x;

    for (int idx = tid; idx < 4 * FIN * HDIM; idx += TPB) {
        int g = idx / (FIN * HDIM);
        int r = idx % (FIN * HDIM);
        int k = r / HDIM, j = r % HDIM;
        sW[g][j][k] = P.Wx[g][k * HDIM + j];
    }
    for (int idx = tid; idx < 4 * HDIM * HDIM; idx += TPB) {
        int g = idx / (HDIM * HDIM);
        int r = idx % (HDIM * HDIM);
        int k = r / HDIM, j = r % HDIM;
        sW[g][j][FIN + k] = P.Wh[g][k * HDIM + j];
    }
    for (int idx = tid; idx < 4 * HDIM; idx += TPB) {
        int g = idx / HDIM, j = idx % HDIM;
        sB[g][j] = P.bx[g][j] + P.bh[g][j] + P.b[g][j];
        sC[g][j] = (g == 2) ? 0.0f : P.wc[g][j];
    }
    for (int idx = tid; idx < HDIM * 12; idx += TPB) {
        int j = idx / 12, m = idx % 12;
        sL[j][m] = (m < OUTD) ? P.Wl[j * OUTD + m] : 0.0f;
    }
    if (tid < 12) sBl[tid] = (tid < OUTD) ? P.bl[tid] : 0.0f;
    __syncthreads();

    const int n = blockIdx.x * TPB + tid;
    if (n >= P.N) return;

    // ---- load x (8) and h (32) as f32x2 pairs ----
    unsigned long long in2[KPAIR];
    {
        const ulonglong2* xp = (const ulonglong2*)(P.x + (size_t)n * FIN);
        ulonglong2 t0 = xp[0], t1 = xp[1];
        in2[0] = t0.x; in2[1] = t0.y; in2[2] = t1.x; in2[3] = t1.y;
        const ulonglong2* hp = (const ulonglong2*)(P.h + (size_t)n * HDIM);
#pragma unroll
        for (int i = 0; i < 8; i++) {
            ulonglong2 t = hp[i];
            in2[4 + 2 * i] = t.x;
            in2[5 + 2 * i] = t.y;
        }
    }
    const float4* c4  = (const float4*)(P.c  + (size_t)n * HDIM);
    float4*       oh4 = (float4*)      (P.h0 + (size_t)n * HDIM);
    float4*       oc4 = (float4*)      (P.c0 + (size_t)n * HDIM);

    float yacc[OUTD];
#pragma unroll
    for (int m = 0; m < OUTD; m++) yacc[m] = sBl[m];

#pragma unroll 1
    for (int jq = 0; jq < HDIM / 4; jq++) {
        float4 cq = c4[jq];
        float cj[4] = {cq.x, cq.y, cq.z, cq.w};
        float h0q[4], c0q[4];

#pragma unroll
        for (int u = 0; u < 4; u++) {
            const int j = jq * 4 + u;
            float s[4];
#pragma unroll
            for (int g = 0; g < 4; g++) {
                const ulonglong2* wr = (const ulonglong2*)&sW[g][j][0];
                unsigned long long acc = 0ULL;
#pragma unroll
                for (int kk = 0; kk < KPAIR / 2; kk++) {   // 10 LDS.128 -> 20 FFMA2
                    ulonglong2 w = wr[kk];
                    ffma2(acc, in2[2 * kk + 0], w.x);
                    ffma2(acc, in2[2 * kk + 1], w.y);
                }
                float lo, hi;
                unpack2(acc, lo, hi);
                s[g] = lo + hi + sB[g][j];
            }
            const float cv = cj[u];
            float ig = sigmoid_f(s[0] + sC[0][j] * cv);
            float fg = sigmoid_f(s[1] + sC[1][j] * cv);
            float tg = tanh_f(s[2]);
            float cc = fg * cv + ig * tg;
            float og = sigmoid_f(s[3] + sC[3][j] * cc);
            float hh = og * tanh_f(cc);
            c0q[u] = cc;
            h0q[u] = hh;
            float r = fmaxf(hh, 0.0f);
#pragma unroll
            for (int m = 0; m < OUTD; m++)
                yacc[m] = fmaf(r, sL[j][m], yacc[m]);
        }
        oh4[jq] = make_float4(h0q[0], h0q[1], h0q[2], h0q[3]);
        oc4[jq] = make_float4(c0q[0], c0q[1], c0q[2], c0q[3]);
    }

    float* oy = P.y + (size_t)n * OUTD;
#pragma unroll
    for (int m = 0; m < OUTD; m++) oy[m] = yacc[m];
}

extern "C" void kernel_launch(void* const* d_in, const int* in_sizes, int n_in,
                              void* d_out, int out_size) {
    (void)n_in; (void)out_size;
    Params P;
    P.x = (const float*)d_in[0];
    // d_in[1] = edge_index, d_in[2] = edge_weight: unused (ChebConv K=1)
    P.h = (const float*)d_in[3];
    P.c = (const float*)d_in[4];
    // gate order: i, f, c, o
    const int wx_idx[4] = {5, 11, 17, 22};
    for (int g = 0; g < 4; g++) {
        int base = wx_idx[g];
        P.Wx[g] = (const float*)d_in[base + 0];
        P.bx[g] = (const float*)d_in[base + 1];
        P.Wh[g] = (const float*)d_in[base + 2];
        P.bh[g] = (const float*)d_in[base + 3];
        P.b[g]  = (const float*)d_in[base + 4];
        P.wc[g] = (g == 2) ? nullptr : (const float*)d_in[base + 5];
    }
    P.Wl = (const float*)d_in[28];
    P.bl = (const float*)d_in[29];

    const int N = in_sizes[0] / FIN;
    P.N = N;
    float* out = (float*)d_out;
    P.y  = out;
    P.h0 = out + (size_t)N * OUTD;
    P.c0 = out + (size_t)N * (OUTD + HDIM);

    const int grid = (N + TPB - 1) / TPB;
    gconv_lstm_kernel<<<grid, TPB>>>(P);
}